// round 1
// baseline (speedup 1.0000x reference)
#include <cuda_runtime.h>
#include <math.h>

// ---------------------------------------------------------------------------
// Problem shapes (fixed by the dataset): T=2048, B=16, D=1024.
//   xw = x @ W_x^T + b   : [T*B, D] = [32768, 1024] fp32 GEMM, K=1024
//   scan: h_t = tanh(xw_t + d_c * h_{t-1})  (elementwise over B*D chains)
//   out  = [ output (T*B*D) | h ((T+1)*B*D) ]
// ---------------------------------------------------------------------------

#define BM 128
#define BN 128
#define BK 8
#define PAD 4

// Scratch for the materialized xw tensor (T*B*D floats = 128 MB).
__device__ float g_xw[2048 * 16 * 1024];

// ---------------------------------------------------------------------------
// GEMM: C[m,n] = sum_k A[m,k] * W[n,k] + bias[n]
// A: [M,K] row-major (x flattened), W: [N,K] row-major, C -> g_xw
// 256 threads, 128x128 block tile, 8x8 per-thread microtile (split 4+4),
// double-buffered shared memory, BK=8.
// ---------------------------------------------------------------------------
__global__ __launch_bounds__(256, 2)
void gemm_xw_kernel(const float* __restrict__ A,
                    const float* __restrict__ W,
                    const float* __restrict__ bias,
                    int M, int N, int K)
{
    __shared__ float As[2][BK][BM + PAD];
    __shared__ float Bs[2][BK][BN + PAD];

    float* __restrict__ C = g_xw;

    const int tid = threadIdx.x;
    const int tx  = tid & 15;   // 0..15 -> N microtile
    const int ty  = tid >> 4;   // 0..15 -> M microtile
    const int m0  = blockIdx.y * BM;
    const int n0  = blockIdx.x * BN;

    // Tile loaders: each thread brings one float4 of A and one of W per k-tile.
    const int lrow = tid >> 1;         // 0..127
    const int lcol = (tid & 1) << 2;   // 0 or 4

    const float* Abase = A + (size_t)(m0 + lrow) * K + lcol;
    const float* Wbase = W + (size_t)(n0 + lrow) * K + lcol;

    float acc[8][8];
#pragma unroll
    for (int i = 0; i < 8; ++i)
#pragma unroll
        for (int j = 0; j < 8; ++j) acc[i][j] = 0.0f;

    // Preload k-tile 0 (transposed into smem: As[k][m], Bs[k][n]).
    {
        float4 a4 = *(const float4*)Abase;
        float4 w4 = *(const float4*)Wbase;
        As[0][lcol + 0][lrow] = a4.x;
        As[0][lcol + 1][lrow] = a4.y;
        As[0][lcol + 2][lrow] = a4.z;
        As[0][lcol + 3][lrow] = a4.w;
        Bs[0][lcol + 0][lrow] = w4.x;
        Bs[0][lcol + 1][lrow] = w4.y;
        Bs[0][lcol + 2][lrow] = w4.z;
        Bs[0][lcol + 3][lrow] = w4.w;
    }
    __syncthreads();

    const int nk = K >> 3;
    for (int kt = 0; kt < nk; ++kt) {
        const int  cur      = kt & 1;
        const bool has_next = (kt + 1 < nk);
        float4 a4n, w4n;
        if (has_next) {
            a4n = *(const float4*)(Abase + (size_t)(kt + 1) * BK);
            w4n = *(const float4*)(Wbase + (size_t)(kt + 1) * BK);
        }

#pragma unroll
        for (int k = 0; k < BK; ++k) {
            float ar[8], br[8];
            *(float4*)&ar[0] = *(const float4*)&As[cur][k][ty * 4];
            *(float4*)&ar[4] = *(const float4*)&As[cur][k][64 + ty * 4];
            *(float4*)&br[0] = *(const float4*)&Bs[cur][k][tx * 4];
            *(float4*)&br[4] = *(const float4*)&Bs[cur][k][64 + tx * 4];
#pragma unroll
            for (int i = 0; i < 8; ++i)
#pragma unroll
                for (int j = 0; j < 8; ++j)
                    acc[i][j] = fmaf(ar[i], br[j], acc[i][j]);
        }

        if (has_next) {
            const int nxt = cur ^ 1;
            As[nxt][lcol + 0][lrow] = a4n.x;
            As[nxt][lcol + 1][lrow] = a4n.y;
            As[nxt][lcol + 2][lrow] = a4n.z;
            As[nxt][lcol + 3][lrow] = a4n.w;
            Bs[nxt][lcol + 0][lrow] = w4n.x;
            Bs[nxt][lcol + 1][lrow] = w4n.y;
            Bs[nxt][lcol + 2][lrow] = w4n.z;
            Bs[nxt][lcol + 3][lrow] = w4n.w;
        }
        __syncthreads();
    }

    // Epilogue: add bias, store as float4 pairs (coalesced across tx lanes).
    float bb[8];
#pragma unroll
    for (int j = 0; j < 4; ++j) {
        bb[j]     = bias[n0 + tx * 4 + j];
        bb[4 + j] = bias[n0 + 64 + tx * 4 + j];
    }
#pragma unroll
    for (int i = 0; i < 8; ++i) {
        const int m = m0 + ((i < 4) ? (ty * 4 + i) : (64 + ty * 4 + (i - 4)));
        float4 v0, v1;
        v0.x = acc[i][0] + bb[0];
        v0.y = acc[i][1] + bb[1];
        v0.z = acc[i][2] + bb[2];
        v0.w = acc[i][3] + bb[3];
        v1.x = acc[i][4] + bb[4];
        v1.y = acc[i][5] + bb[5];
        v1.z = acc[i][6] + bb[6];
        v1.w = acc[i][7] + bb[7];
        *(float4*)(C + (size_t)m * N + n0 + tx * 4)      = v0;
        *(float4*)(C + (size_t)m * N + n0 + 64 + tx * 4) = v1;
    }
}

// ---------------------------------------------------------------------------
// Recurrent scan: 1 thread per (b,e) chain; T sequential steps.
// tanh via e^{2|z|}: abs err ~1e-7 (MUFU.TANH's ~5e-4 is too close to the
// 1e-3 correctness gate). Loads/stores are off the dependency chain.
// ---------------------------------------------------------------------------
__global__ void scan_kernel(const float* __restrict__ h0,
                            const float* __restrict__ dvec,
                            float* __restrict__ out,
                            int T, int BD, int D)
{
    const int idx = blockIdx.x * blockDim.x + threadIdx.x;
    if (idx >= BD) return;

    const int e = idx % D;
    float dc = dvec[e];
    dc = fminf(fmaxf(dc, -0.99f), 0.99f);

    float h = h0[idx];
    float* __restrict__ out_h = out + (size_t)T * BD;   // h block after output
    out_h[idx] = h;                                      // h[0] = h0

    const float* __restrict__ p = g_xw + idx;

    for (int t = 0; t < T; ++t) {
        const float a  = p[(size_t)t * BD];
        const float z  = fmaf(dc, h, a);
        // tanh(z) = sign(z) * (1 - 2 / (e^{2|z|} + 1))
        const float az = fabsf(z);
        const float ex = __expf(az + az);
        const float th = 1.0f - __fdividef(2.0f, ex + 1.0f);
        h = copysignf(th, z);

        // out = h * silu(h) = h^2 * sigmoid(h)   (off the dependency chain)
        const float s = __fdividef(1.0f, 1.0f + __expf(-h));
        out[(size_t)t * BD + idx]         = h * h * s;
        out_h[(size_t)(t + 1) * BD + idx] = h;
    }
}

// ---------------------------------------------------------------------------
// kernel_launch: GEMM then scan, same (default) stream — graph-capturable.
// Inputs (metadata order): x [T,B,D], h0 [B,D], W_x [D,D], d [D], b [D].
// ---------------------------------------------------------------------------
extern "C" void kernel_launch(void* const* d_in, const int* in_sizes, int n_in,
                              void* d_out, int out_size)
{
    (void)n_in; (void)out_size;

    const float* x  = (const float*)d_in[0];
    const float* h0 = (const float*)d_in[1];
    const float* W  = (const float*)d_in[2];
    const float* dv = (const float*)d_in[3];
    const float* b  = (const float*)d_in[4];
    float* out = (float*)d_out;

    const int D  = in_sizes[3];             // 1024
    const int BD = in_sizes[1];             // B*D = 16384
    const int T  = in_sizes[0] / BD;        // 2048
    const int M  = in_sizes[0] / D;         // T*B = 32768

    dim3 gGrid(D / BN, M / BM);             // (8, 256)
    gemm_xw_kernel<<<gGrid, 256>>>(x, W, b, M, D, D);

    const int threads = 128;
    scan_kernel<<<(BD + threads - 1) / threads, threads>>>(h0, dv, out, T, BD, D);
}

// round 3
// speedup vs baseline: 1.8316x; 1.8316x over previous
#include <cuda_runtime.h>
#include <cuda_bf16.h>
#include <cstdint>
#include <math.h>

// ---------------------------------------------------------------------------
// Shapes (fixed): T=2048, B=16, D=1024.  M = T*B = 32768, K = N = 1024.
//   xw = x @ W_x^T + b  via mma.sync bf16 hi/lo split (3 MMAs), fp32 accum
//   scan: h_t = tanh(xw_t + d_c * h_{t-1}); out_t = h_t^2 * sigmoid(h_t)
//   d_out = [ output (T*B*D) | h ((T+1)*B*D) ]
// NOTE: tcgen05 is NOT usable — harness PTX target is plain sm_103 (no 'a'),
// so only baseline-ISA tensor ops (mma.sync / ldmatrix / cp.async) compile.
// ---------------------------------------------------------------------------

#define KDIM 1024
#define BM 128
#define BN 128
#define BK 64                 // 64 bf16 = 128 B rows -> SW128 swizzle
#define NK (KDIM / BK)        // 16

// Scratch (device globals: allocation-guard safe)
__device__ __align__(128) float         g_xw [2048 * 16 * 1024];  // 128 MB
__device__ __align__(128) __nv_bfloat16 g_Ahi[32768 * 1024];      // 64 MB
__device__ __align__(128) __nv_bfloat16 g_Alo[32768 * 1024];      // 64 MB
__device__ __align__(128) __nv_bfloat16 g_Whi[1024 * 1024];       // 2 MB
__device__ __align__(128) __nv_bfloat16 g_Wlo[1024 * 1024];       // 2 MB

// ---------------------------------------------------------------------------
// fp32 -> bf16 hi/lo split converters
// ---------------------------------------------------------------------------
__device__ __forceinline__ void split4(float4 v, uint2& hi, uint2& lo) {
    __nv_bfloat16 hx = __float2bfloat16(v.x), hy = __float2bfloat16(v.y);
    __nv_bfloat16 hz = __float2bfloat16(v.z), hw = __float2bfloat16(v.w);
    __nv_bfloat16 lx = __float2bfloat16(v.x - __bfloat162float(hx));
    __nv_bfloat16 ly = __float2bfloat16(v.y - __bfloat162float(hy));
    __nv_bfloat16 lz = __float2bfloat16(v.z - __bfloat162float(hz));
    __nv_bfloat16 lw = __float2bfloat16(v.w - __bfloat162float(hw));
    __nv_bfloat162 h01 = __halves2bfloat162(hx, hy), h23 = __halves2bfloat162(hz, hw);
    __nv_bfloat162 l01 = __halves2bfloat162(lx, ly), l23 = __halves2bfloat162(lz, lw);
    hi.x = *reinterpret_cast<uint32_t*>(&h01); hi.y = *reinterpret_cast<uint32_t*>(&h23);
    lo.x = *reinterpret_cast<uint32_t*>(&l01); lo.y = *reinterpret_cast<uint32_t*>(&l23);
}
__global__ void splitA_kernel(const float4* __restrict__ src, int n4) {
    int i = blockIdx.x * blockDim.x + threadIdx.x;
    if (i >= n4) return;
    uint2 hi, lo; split4(src[i], hi, lo);
    reinterpret_cast<uint2*>(g_Ahi)[i] = hi;
    reinterpret_cast<uint2*>(g_Alo)[i] = lo;
}
__global__ void splitW_kernel(const float4* __restrict__ src, int n4) {
    int i = blockIdx.x * blockDim.x + threadIdx.x;
    if (i >= n4) return;
    uint2 hi, lo; split4(src[i], hi, lo);
    reinterpret_cast<uint2*>(g_Whi)[i] = hi;
    reinterpret_cast<uint2*>(g_Wlo)[i] = lo;
}

// ---------------------------------------------------------------------------
// PTX helpers (baseline ISA only)
// ---------------------------------------------------------------------------
__device__ __forceinline__ uint32_t smem_u32(const void* p) {
    uint32_t a;
    asm("{ .reg .u64 t; cvta.to.shared.u64 t, %1; cvt.u32.u64 %0, t; }" : "=r"(a) : "l"(p));
    return a;
}
__device__ __forceinline__ void cp16(uint32_t dst, const void* src) {
    asm volatile("cp.async.cg.shared.global [%0], [%1], 16;" :: "r"(dst), "l"(src));
}
#define CP_COMMIT() asm volatile("cp.async.commit_group;" ::: "memory")
#define CP_WAIT(n)  asm volatile("cp.async.wait_group %0;" :: "n"(n) : "memory")

__device__ __forceinline__ void ldm_x4(uint32_t* r, uint32_t addr) {
    asm volatile("ldmatrix.sync.aligned.m8n8.x4.shared.b16 {%0,%1,%2,%3}, [%4];"
                 : "=r"(r[0]), "=r"(r[1]), "=r"(r[2]), "=r"(r[3]) : "r"(addr));
}
__device__ __forceinline__ void mma16816(float* d, const uint32_t* a,
                                         const uint32_t* b) {
    asm volatile(
        "mma.sync.aligned.m16n8k16.row.col.f32.bf16.bf16.f32 "
        "{%0,%1,%2,%3}, {%4,%5,%6,%7}, {%8,%9}, {%0,%1,%2,%3};"
        : "+f"(d[0]), "+f"(d[1]), "+f"(d[2]), "+f"(d[3])
        : "r"(a[0]), "r"(a[1]), "r"(a[2]), "r"(a[3]), "r"(b[0]), "r"(b[1]));
}

// SMEM: per stage: Ahi(16K) Alo(16K) Bhi(16K) Blo(16K) = 64 KB; 2 stages.
#define STG_BYTES   (64 * 1024)
#define OFF_AH      0
#define OFF_AL      (16 * 1024)
#define OFF_BH      (32 * 1024)
#define OFF_BL      (48 * 1024)
#define SMEM_TOTAL  (2 * STG_BYTES)

// Swizzled byte offset for (row, 16B-chunk c) in a 128-row x 128-byte tile.
__device__ __forceinline__ uint32_t tswz(int row, int c) {
    return (uint32_t)(row * 128 + ((c ^ (row & 7)) * 16));
}

// ---------------------------------------------------------------------------
// GEMM: g_xw[m,n] = sum_k A[m,k]*W[n,k] + bias[n]
// 256 threads (8 warps: warp_m = wid&3 over 32 rows, warp_n = wid>>2 over 64)
// ---------------------------------------------------------------------------
__global__ __launch_bounds__(256, 1)
void gemm_mma_kernel(const float* __restrict__ bias) {
    extern __shared__ char smem[];
    const uint32_t sb = smem_u32(smem);
    const int tid = threadIdx.x;
    const int wid = tid >> 5;
    const int lane = tid & 31;
    const int m0 = blockIdx.y * BM;
    const int n0 = blockIdx.x * BN;

    const int warp_m = wid & 3;    // 0..3 -> 32 rows
    const int warp_n = wid >> 2;   // 0..1 -> 64 cols

    // Loader mapping: row = tid>>1 (0..127), chunks (tid&1)*4 .. +3
    const int lrow = tid >> 1;
    const int lc0  = (tid & 1) * 4;

    auto stage_in = [&](int kt, int stg) {
        const uint32_t base = sb + stg * STG_BYTES;
        const size_t ga = (size_t)(m0 + lrow) * KDIM + kt * BK;
        const size_t gb = (size_t)(n0 + lrow) * KDIM + kt * BK;
#pragma unroll
        for (int j = 0; j < 4; ++j) {
            const int c = lc0 + j;
            const uint32_t so = tswz(lrow, c);
            cp16(base + OFF_AH + so, g_Ahi + ga + c * 8);
            cp16(base + OFF_AL + so, g_Alo + ga + c * 8);
            cp16(base + OFF_BH + so, g_Whi + gb + c * 8);
            cp16(base + OFF_BL + so, g_Wlo + gb + c * 8);
        }
        CP_COMMIT();
    };

    float acc[2][8][4];
#pragma unroll
    for (int i = 0; i < 2; ++i)
#pragma unroll
        for (int j = 0; j < 8; ++j)
#pragma unroll
            for (int q = 0; q < 4; ++q) acc[i][j][q] = 0.0f;

    stage_in(0, 0);

    // ldmatrix lane decomposition
    const int lmat = lane >> 3;      // matrix index 0..3
    const int lrow8 = lane & 7;      // row within 8x8 matrix

    for (int kt = 0; kt < NK; ++kt) {
        if (kt + 1 < NK) stage_in(kt + 1, (kt + 1) & 1);
        if (kt + 1 < NK) { CP_WAIT(1); } else { CP_WAIT(0); }
        __syncthreads();

        const uint32_t base = sb + (kt & 1) * STG_BYTES;

#pragma unroll
        for (int kk = 0; kk < 4; ++kk) {   // four k16 steps in BK=64
            // A fragments: 2 m-tiles (16 rows each) x {hi, lo}
            uint32_t afh[2][4], afl[2][4];
#pragma unroll
            for (int mt = 0; mt < 2; ++mt) {
                const int r = warp_m * 32 + mt * 16 + (lmat & 1) * 8 + lrow8;
                const int c = 2 * kk + (lmat >> 1);
                const uint32_t so = tswz(r, c);
                ldm_x4(afh[mt], base + OFF_AH + so);
                ldm_x4(afl[mt], base + OFF_AL + so);
            }
            // B fragments: 4 n16-tiles x {hi, lo}; regs {b0t0,b1t0,b0t1,b1t1}
            uint32_t bfh[4][4], bfl[4][4];
#pragma unroll
            for (int bt = 0; bt < 4; ++bt) {
                const int r = warp_n * 64 + bt * 16 + (lmat >> 1) * 8 + lrow8;
                const int c = 2 * kk + (lmat & 1);
                const uint32_t so = tswz(r, c);
                ldm_x4(bfh[bt], base + OFF_BH + so);
                ldm_x4(bfl[bt], base + OFF_BL + so);
            }
#pragma unroll
            for (int mt = 0; mt < 2; ++mt)
#pragma unroll
                for (int nt = 0; nt < 8; ++nt) {
                    const int bt = nt >> 1;
                    const int bo = (nt & 1) * 2;
                    mma16816(acc[mt][nt], afh[mt], &bfh[bt][bo]);   // hi*hi
                    mma16816(acc[mt][nt], afh[mt], &bfl[bt][bo]);   // hi*lo
                    mma16816(acc[mt][nt], afl[mt], &bfh[bt][bo]);   // lo*hi
                }
        }
        __syncthreads();
    }

    // Epilogue: add bias, store fp32 to g_xw
    const int g   = lane >> 2;
    const int tig = lane & 3;
#pragma unroll
    for (int mt = 0; mt < 2; ++mt) {
#pragma unroll
        for (int nt = 0; nt < 8; ++nt) {
            const int row = m0 + warp_m * 32 + mt * 16 + g;
            const int col = n0 + warp_n * 64 + nt * 8 + tig * 2;
            const float b0 = __ldg(bias + col);
            const float b1 = __ldg(bias + col + 1);
            float2 v0 = make_float2(acc[mt][nt][0] + b0, acc[mt][nt][1] + b1);
            float2 v1 = make_float2(acc[mt][nt][2] + b0, acc[mt][nt][3] + b1);
            *reinterpret_cast<float2*>(g_xw + (size_t)row * KDIM + col)       = v0;
            *reinterpret_cast<float2*>(g_xw + (size_t)(row + 8) * KDIM + col) = v1;
        }
    }
}

// ---------------------------------------------------------------------------
// Recurrent scan: 1 thread per (b,e) chain; prefetch 16 xw values ahead so
// the DRAM load latency is off the tanh dependency chain.
// ---------------------------------------------------------------------------
#define PF 16
__global__ void scan_kernel(const float* __restrict__ h0,
                            const float* __restrict__ dvec,
                            float* __restrict__ out,
                            int T, int BD, int D)
{
    const int idx = blockIdx.x * blockDim.x + threadIdx.x;
    if (idx >= BD) return;

    float dc = dvec[idx & (D - 1)];
    dc = fminf(fmaxf(dc, -0.99f), 0.99f);

    float h = h0[idx];
    float* __restrict__ out_h = out + (size_t)T * BD;
    out_h[idx] = h;

    const float* __restrict__ p = g_xw + idx;
    const size_t s = (size_t)BD;

    float cur[PF];
#pragma unroll
    for (int u = 0; u < PF; ++u) cur[u] = p[u * s];

    for (int t0 = 0; t0 < T; t0 += PF) {
        float nxt[PF];
        if (t0 + PF < T) {
            const float* pn = p + (size_t)(t0 + PF) * s;
#pragma unroll
            for (int u = 0; u < PF; ++u) nxt[u] = pn[u * s];
        } else {
#pragma unroll
            for (int u = 0; u < PF; ++u) nxt[u] = 0.0f;
        }
        float* __restrict__ po = out + (size_t)t0 * BD + idx;
        float* __restrict__ ph = out_h + (size_t)(t0 + 1) * BD + idx;
#pragma unroll
        for (int u = 0; u < PF; ++u) {
            const float z  = fmaf(dc, h, cur[u]);
            const float ex = __expf(z + z);                 // inf/0 at saturation: OK
            h = 1.0f - __fdividef(2.0f, ex + 1.0f);         // tanh(z)
            const float sg = __fdividef(1.0f, 1.0f + __expf(-h));
            po[(size_t)u * BD] = h * h * sg;                // h * silu(h)
            ph[(size_t)u * BD] = h;
        }
#pragma unroll
        for (int u = 0; u < PF; ++u) cur[u] = nxt[u];
    }
}

// ---------------------------------------------------------------------------
// kernel_launch: split -> GEMM -> scan (one stream, graph-capturable)
// ---------------------------------------------------------------------------
extern "C" void kernel_launch(void* const* d_in, const int* in_sizes, int n_in,
                              void* d_out, int out_size)
{
    (void)n_in; (void)out_size;
    const float* x  = (const float*)d_in[0];
    const float* h0 = (const float*)d_in[1];
    const float* W  = (const float*)d_in[2];
    const float* dv = (const float*)d_in[3];
    const float* b  = (const float*)d_in[4];
    float* out = (float*)d_out;

    const int D  = in_sizes[3];           // 1024
    const int BD = in_sizes[1];           // 16384
    const int T  = in_sizes[0] / BD;      // 2048
    const int M  = in_sizes[0] / D;       // 32768

    const int nA4 = (M * D) / 4;
    splitA_kernel<<<nA4 / 256, 256>>>((const float4*)x, nA4);
    const int nW4 = (D * D) / 4;
    splitW_kernel<<<(nW4 + 255) / 256, 256>>>((const float4*)W, nW4);

    static int smem_set = 0;
    if (!smem_set) {
        cudaFuncSetAttribute(gemm_mma_kernel,
                             cudaFuncAttributeMaxDynamicSharedMemorySize, SMEM_TOTAL);
        smem_set = 1;
    }
    dim3 grid(D / BN, M / BM);            // (8, 256)
    gemm_mma_kernel<<<grid, 256, SMEM_TOTAL>>>(b);

    scan_kernel<<<(BD + 127) / 128, 128>>>(h0, dv, out, T, BD, D);
}

// round 4
// speedup vs baseline: 1.8578x; 1.0143x over previous
#include <cuda_runtime.h>
#include <cuda_bf16.h>
#include <cstdint>
#include <math.h>

// ---------------------------------------------------------------------------
// Shapes (fixed): T=2048, B=16, D=1024.  M = T*B = 32768, K = N = 1024.
//   xw = x @ W_x^T + b  via mma.sync bf16 hi/lo split (3 MMAs), fp32 accum.
//   A (=x) is split fp32->bf16 hi/lo INSIDE the GEMM (register convert + STS),
//   W is pre-split once (4 MB).
//   scan: h_t = tanh(xw_t + d_c * h_{t-1}); out_t = h_t^2 * sigmoid(h_t)
//   d_out = [ output (T*B*D) | h ((T+1)*B*D) ]
// ---------------------------------------------------------------------------

#define KDIM 1024
#define BM 128
#define BN 128
#define BK 64                 // 64 bf16 = 128 B rows -> SW128-style swizzle
#define NK (KDIM / BK)        // 16

// Scratch (device globals: allocation-guard safe)
__device__ __align__(128) float         g_xw [2048 * 16 * 1024];  // 128 MB
__device__ __align__(128) __nv_bfloat16 g_Whi[1024 * 1024];       // 2 MB
__device__ __align__(128) __nv_bfloat16 g_Wlo[1024 * 1024];       // 2 MB

// ---------------------------------------------------------------------------
// fp32 -> bf16 hi/lo split
// ---------------------------------------------------------------------------
__device__ __forceinline__ void split4(float4 v, uint2& hi, uint2& lo) {
    __nv_bfloat16 hx = __float2bfloat16(v.x), hy = __float2bfloat16(v.y);
    __nv_bfloat16 hz = __float2bfloat16(v.z), hw = __float2bfloat16(v.w);
    __nv_bfloat16 lx = __float2bfloat16(v.x - __bfloat162float(hx));
    __nv_bfloat16 ly = __float2bfloat16(v.y - __bfloat162float(hy));
    __nv_bfloat16 lz = __float2bfloat16(v.z - __bfloat162float(hz));
    __nv_bfloat16 lw = __float2bfloat16(v.w - __bfloat162float(hw));
    __nv_bfloat162 h01 = __halves2bfloat162(hx, hy), h23 = __halves2bfloat162(hz, hw);
    __nv_bfloat162 l01 = __halves2bfloat162(lx, ly), l23 = __halves2bfloat162(lz, lw);
    hi.x = *reinterpret_cast<uint32_t*>(&h01); hi.y = *reinterpret_cast<uint32_t*>(&h23);
    lo.x = *reinterpret_cast<uint32_t*>(&l01); lo.y = *reinterpret_cast<uint32_t*>(&l23);
}
__global__ void splitW_kernel(const float4* __restrict__ src, int n4) {
    int i = blockIdx.x * blockDim.x + threadIdx.x;
    if (i >= n4) return;
    uint2 hi, lo; split4(src[i], hi, lo);
    reinterpret_cast<uint2*>(g_Whi)[i] = hi;
    reinterpret_cast<uint2*>(g_Wlo)[i] = lo;
}

// ---------------------------------------------------------------------------
// PTX helpers (baseline ISA only — tcgen05 NOT available at sm_103 target)
// ---------------------------------------------------------------------------
__device__ __forceinline__ uint32_t smem_u32(const void* p) {
    uint32_t a;
    asm("{ .reg .u64 t; cvta.to.shared.u64 t, %1; cvt.u32.u64 %0, t; }" : "=r"(a) : "l"(p));
    return a;
}
__device__ __forceinline__ void cp16(uint32_t dst, const void* src) {
    asm volatile("cp.async.cg.shared.global [%0], [%1], 16;" :: "r"(dst), "l"(src));
}
#define CP_COMMIT() asm volatile("cp.async.commit_group;" ::: "memory")
#define CP_WAIT(n)  asm volatile("cp.async.wait_group %0;" :: "n"(n) : "memory")

__device__ __forceinline__ void ldm_x4(uint32_t* r, uint32_t addr) {
    asm volatile("ldmatrix.sync.aligned.m8n8.x4.shared.b16 {%0,%1,%2,%3}, [%4];"
                 : "=r"(r[0]), "=r"(r[1]), "=r"(r[2]), "=r"(r[3]) : "r"(addr));
}
__device__ __forceinline__ void mma16816(float* d, const uint32_t* a,
                                         const uint32_t* b) {
    asm volatile(
        "mma.sync.aligned.m16n8k16.row.col.f32.bf16.bf16.f32 "
        "{%0,%1,%2,%3}, {%4,%5,%6,%7}, {%8,%9}, {%0,%1,%2,%3};"
        : "+f"(d[0]), "+f"(d[1]), "+f"(d[2]), "+f"(d[3])
        : "r"(a[0]), "r"(a[1]), "r"(a[2]), "r"(a[3]), "r"(b[0]), "r"(b[1]));
}

// SMEM: per stage: Ahi(16K) Alo(16K) Whi(16K) Wlo(16K) = 64 KB; 2 stages.
#define STG_BYTES   (64 * 1024)
#define OFF_AH      0
#define OFF_AL      (16 * 1024)
#define OFF_BH      (32 * 1024)
#define OFF_BL      (48 * 1024)
#define SMEM_TOTAL  (2 * STG_BYTES)

// Swizzled byte offset for (row, 16B-chunk c) in a 128-row x 128-byte tile.
__device__ __forceinline__ uint32_t tswz(int row, int c) {
    return (uint32_t)(row * 128 + ((c ^ (row & 7)) * 16));
}

// ---------------------------------------------------------------------------
// GEMM: g_xw[m,n] = sum_k x[m,k]*W[n,k] + bias[n]
// 256 threads (8 warps: warp_m = wid&3 over 32 rows, warp_n = wid>>2 over 64)
// A: LDG fp32 -> reg convert -> STS bf16 hi/lo.  W: cp.async pre-split bf16.
// ---------------------------------------------------------------------------
__global__ __launch_bounds__(256, 1)
void gemm_mma_kernel(const float* __restrict__ x, const float* __restrict__ bias) {
    extern __shared__ char smem[];
    const uint32_t sb = smem_u32(smem);
    const int tid = threadIdx.x;
    const int wid = tid >> 5;
    const int lane = tid & 31;
    const int m0 = blockIdx.y * BM;
    const int n0 = blockIdx.x * BN;

    const int warp_m = wid & 3;    // 0..3 -> 32 rows
    const int warp_n = wid >> 2;   // 0..1 -> 64 cols

    // Loader mapping: row = tid>>1 (0..127), 16B chunks (tid&1)*4 .. +3
    const int lrow = tid >> 1;
    const int lc0  = (tid & 1) * 4;

    // W stage-in via cp.async (bf16 pre-split)
    auto stageW = [&](int kt, int stg) {
        const uint32_t base = sb + stg * STG_BYTES;
        const size_t gb = (size_t)(n0 + lrow) * KDIM + kt * BK;
#pragma unroll
        for (int j = 0; j < 4; ++j) {
            const int c = lc0 + j;
            const uint32_t so = tswz(lrow, c);
            cp16(base + OFF_BH + so, g_Whi + gb + c * 8);
            cp16(base + OFF_BL + so, g_Wlo + gb + c * 8);
        }
        CP_COMMIT();
    };
    // A: LDG fp32 tile slice (32 floats = 8 float4) into regs
    auto ldgA = [&](int kt, float4* a8) {
        const float4* src = reinterpret_cast<const float4*>(
            x + (size_t)(m0 + lrow) * KDIM + kt * BK + lc0 * 8);
#pragma unroll
        for (int j = 0; j < 8; ++j) a8[j] = __ldg(src + j);
    };
    // A: reg convert -> STS swizzled bf16 hi/lo
    auto cvtA = [&](const float4* a8, int stg) {
        char* base = smem + stg * STG_BYTES;
#pragma unroll
        for (int j = 0; j < 4; ++j) {
            uint2 h0, l0, h1, l1;
            split4(a8[2 * j], h0, l0);
            split4(a8[2 * j + 1], h1, l1);
            const uint32_t so = tswz(lrow, lc0 + j);
            *reinterpret_cast<uint4*>(base + OFF_AH + so) = make_uint4(h0.x, h0.y, h1.x, h1.y);
            *reinterpret_cast<uint4*>(base + OFF_AL + so) = make_uint4(l0.x, l0.y, l1.x, l1.y);
        }
    };

    float acc[2][8][4];
#pragma unroll
    for (int i = 0; i < 2; ++i)
#pragma unroll
        for (int j = 0; j < 8; ++j)
#pragma unroll
            for (int q = 0; q < 4; ++q) acc[i][j][q] = 0.0f;

    // Prologue: stage 0
    {
        float4 a8[8];
        ldgA(0, a8);
        stageW(0, 0);
        cvtA(a8, 0);
        CP_WAIT(0);
        __syncthreads();
    }

    const int lmat  = lane >> 3;     // matrix index 0..3
    const int lrow8 = lane & 7;      // row within 8x8 matrix

    for (int kt = 0; kt < NK; ++kt) {
        const int stg = kt & 1;
        const bool more = (kt + 1 < NK);
        float4 a8[8];
        if (more) { ldgA(kt + 1, a8); stageW(kt + 1, stg ^ 1); }

        const uint32_t base = sb + stg * STG_BYTES;
#pragma unroll
        for (int kk = 0; kk < 4; ++kk) {   // four k16 steps in BK=64
            uint32_t afh[2][4], afl[2][4];
#pragma unroll
            for (int mt = 0; mt < 2; ++mt) {
                const int r = warp_m * 32 + mt * 16 + (lmat & 1) * 8 + lrow8;
                const int c = 2 * kk + (lmat >> 1);
                const uint32_t so = tswz(r, c);
                ldm_x4(afh[mt], base + OFF_AH + so);
                ldm_x4(afl[mt], base + OFF_AL + so);
            }
            uint32_t bfh[4][4], bfl[4][4];
#pragma unroll
            for (int bt = 0; bt < 4; ++bt) {
                const int r = warp_n * 64 + bt * 16 + (lmat >> 1) * 8 + lrow8;
                const int c = 2 * kk + (lmat & 1);
                const uint32_t so = tswz(r, c);
                ldm_x4(bfh[bt], base + OFF_BH + so);
                ldm_x4(bfl[bt], base + OFF_BL + so);
            }
#pragma unroll
            for (int mt = 0; mt < 2; ++mt)
#pragma unroll
                for (int nt = 0; nt < 8; ++nt) {
                    const int bt = nt >> 1;
                    const int bo = (nt & 1) * 2;
                    mma16816(acc[mt][nt], afh[mt], &bfh[bt][bo]);   // hi*hi
                    mma16816(acc[mt][nt], afh[mt], &bfl[bt][bo]);   // hi*lo
                    mma16816(acc[mt][nt], afl[mt], &bfh[bt][bo]);   // lo*hi
                }
        }

        if (more) {
            cvtA(a8, stg ^ 1);   // stage^1 was last read at kt-1 (done pre-sync)
            CP_WAIT(0);
        }
        __syncthreads();
    }

    // Epilogue: add bias, store fp32 to g_xw
    const int g   = lane >> 2;
    const int tig = lane & 3;
#pragma unroll
    for (int mt = 0; mt < 2; ++mt) {
#pragma unroll
        for (int nt = 0; nt < 8; ++nt) {
            const int row = m0 + warp_m * 32 + mt * 16 + g;
            const int col = n0 + warp_n * 64 + nt * 8 + tig * 2;
            const float b0 = __ldg(bias + col);
            const float b1 = __ldg(bias + col + 1);
            float2 v0 = make_float2(acc[mt][nt][0] + b0, acc[mt][nt][1] + b1);
            float2 v1 = make_float2(acc[mt][nt][2] + b0, acc[mt][nt][3] + b1);
            *reinterpret_cast<float2*>(g_xw + (size_t)row * KDIM + col)       = v0;
            *reinterpret_cast<float2*>(g_xw + (size_t)(row + 8) * KDIM + col) = v1;
        }
    }
}

// ---------------------------------------------------------------------------
// Recurrent scan: 1 thread per (b,e) chain; prefetch 16 xw values ahead.
// Precise tanh (exp+rcp) for the recurrence; tanh.approx for the OUTPUT
// sigmoid only (error does not feed back). Streaming cache hints.
// 64 blocks x 256 threads -> 2 warps/SMSP for latency overlap.
// ---------------------------------------------------------------------------
#define PF 16
__global__ __launch_bounds__(256)
void scan_kernel(const float* __restrict__ h0,
                 const float* __restrict__ dvec,
                 float* __restrict__ out,
                 int T, int BD, int D)
{
    const int idx = blockIdx.x * blockDim.x + threadIdx.x;
    if (idx >= BD) return;

    float dc = dvec[idx & (D - 1)];
    dc = fminf(fmaxf(dc, -0.99f), 0.99f);

    float h = h0[idx];
    float* __restrict__ out_h = out + (size_t)T * BD;
    __stcs(out_h + idx, h);

    const float* __restrict__ p = g_xw + idx;
    const size_t s = (size_t)BD;

    float cur[PF];
#pragma unroll
    for (int u = 0; u < PF; ++u) cur[u] = __ldcs(p + u * s);

    for (int t0 = 0; t0 < T; t0 += PF) {
        float nxt[PF];
        if (t0 + PF < T) {
            const float* pn = p + (size_t)(t0 + PF) * s;
#pragma unroll
            for (int u = 0; u < PF; ++u) nxt[u] = __ldcs(pn + u * s);
        } else {
#pragma unroll
            for (int u = 0; u < PF; ++u) nxt[u] = 0.0f;
        }
        float* __restrict__ po = out + (size_t)t0 * BD + idx;
        float* __restrict__ ph = out_h + (size_t)(t0 + 1) * BD + idx;
#pragma unroll
        for (int u = 0; u < PF; ++u) {
            const float z  = fmaf(dc, h, cur[u]);
            const float ex = __expf(z + z);                 // inf/0 at saturation: OK
            h = 1.0f - __fdividef(2.0f, ex + 1.0f);         // precise tanh(z)
            // sigmoid(h) = 0.5 + 0.5*tanh(h/2) -- approx OK (output-only)
            float th;
            asm("tanh.approx.f32 %0, %1;" : "=f"(th) : "f"(0.5f * h));
            const float sg = fmaf(0.5f, th, 0.5f);
            __stcs(po + (size_t)u * BD, h * h * sg);        // h * silu(h)
            __stcs(ph + (size_t)u * BD, h);
        }
#pragma unroll
        for (int u = 0; u < PF; ++u) cur[u] = nxt[u];
    }
}

// ---------------------------------------------------------------------------
// kernel_launch: splitW -> GEMM -> scan (one stream, graph-capturable)
// ---------------------------------------------------------------------------
extern "C" void kernel_launch(void* const* d_in, const int* in_sizes, int n_in,
                              void* d_out, int out_size)
{
    (void)n_in; (void)out_size;
    const float* x  = (const float*)d_in[0];
    const float* h0 = (const float*)d_in[1];
    const float* W  = (const float*)d_in[2];
    const float* dv = (const float*)d_in[3];
    const float* b  = (const float*)d_in[4];
    float* out = (float*)d_out;

    const int D  = in_sizes[3];           // 1024
    const int BD = in_sizes[1];           // 16384
    const int T  = in_sizes[0] / BD;      // 2048
    const int M  = in_sizes[0] / D;       // 32768

    const int nW4 = (D * D) / 4;
    splitW_kernel<<<(nW4 + 255) / 256, 256>>>((const float4*)W, nW4);

    cudaFuncSetAttribute(gemm_mma_kernel,
                         cudaFuncAttributeMaxDynamicSharedMemorySize, SMEM_TOTAL);
    dim3 grid(D / BN, M / BM);            // (8, 256)
    gemm_mma_kernel<<<grid, 256, SMEM_TOTAL>>>(x, b);

    scan_kernel<<<64, 256>>>(h0, dv, out, T, BD, D);
}